// round 12
// baseline (speedup 1.0000x reference)
#include <cuda_runtime.h>
#include <cstdint>

// N=100000 nodes, D=64 feats, E=1250000 edges, W=1024, T=20000 targets.
static constexpr int N_NODES = 100000;
static constexpr int D4 = 16;       // float4 per row (64 floats)
static constexpr int CAP = 64;      // per-node bin capacity (P(deg>=64) ~ 1e-23)

// One persistent wave: 16 blocks/SM x 148 SMs, 128 thr, 32 regs (forced).
static constexpr int NBLOCKS  = 2368;   // 148 * 16
static constexpr int NTHREADS = 128;
static constexpr int TOTAL_THREADS = NBLOCKS * NTHREADS;          // 303104
static constexpr int TOTAL_WARPS   = TOTAL_THREADS / 32;          // 9472

// Packed edge entry: src in bits [0,17), widx in bits [17,27).
static constexpr int SRC_BITS = 17;
static constexpr unsigned SRC_MASK = (1u << SRC_BITS) - 1u;

// Scratch. Zero-initialized at load; phase B resets count/flag per node.
__device__ int      g_count[N_NODES];
__device__ int      g_flag[N_NODES];
__device__ unsigned g_bins[(size_t)N_NODES * CAP];   // packed (widx<<17)|src

// Grid barrier state (sense-reversal; persists correctly across replays).
__device__ unsigned g_bar   = 0;
__device__ unsigned g_sense = 0;

// x gather: bypass L1 (streaming) -> L2 only
__device__ __forceinline__ float4 ld_cg_f4(const float4* p) {
    float4 r;
    asm volatile("ld.global.cg.v4.f32 {%0, %1, %2, %3}, [%4];"
                 : "=f"(r.x), "=f"(r.y), "=f"(r.z), "=f"(r.w) : "l"(p));
    return r;
}
// w gather: cache in L1 (256KB hot working set)
__device__ __forceinline__ float4 ld_ca_f4(const float4* p) {
    float4 r;
    asm volatile("ld.global.ca.v4.f32 {%0, %1, %2, %3}, [%4];"
                 : "=f"(r.x), "=f"(r.y), "=f"(r.z), "=f"(r.w) : "l"(p));
    return r;
}

// ---------------------------------------------------------------------------
// Fused persistent kernel: scatter -> grid barrier -> accumulate.
// Single resident wave (2368 blocks * 128 thr @ 32 regs), so the software
// barrier cannot deadlock: every block is scheduled.
// ---------------------------------------------------------------------------
__global__ void __launch_bounds__(NTHREADS, 16)
fused_kernel(const float4* __restrict__ x4,
             const float4* __restrict__ w4,
             const int* __restrict__ u,
             const int* __restrict__ v,
             const int* __restrict__ widx,
             const int* __restrict__ targets,
             float4* __restrict__ out4,
             int n_edges, int n_targets) {
    const int gtid = blockIdx.x * blockDim.x + threadIdx.x;

    // ---------------- Phase A: bin edges by destination + target flags ----
    {
        int nquads = n_edges >> 2;
        for (int q = gtid; q < nquads; q += TOTAL_THREADS) {
            int e = q << 2;
            int4 uu = *(const int4*)(u + e);
            int4 vv = *(const int4*)(v + e);
            int4 ww = *(const int4*)(widx + e);
            unsigned c0 = ((unsigned)ww.x << SRC_BITS) | (unsigned)uu.x;
            unsigned c1 = ((unsigned)ww.y << SRC_BITS) | (unsigned)uu.y;
            unsigned c2 = ((unsigned)ww.z << SRC_BITS) | (unsigned)uu.z;
            unsigned c3 = ((unsigned)ww.w << SRC_BITS) | (unsigned)uu.w;
            int p0 = atomicAdd(&g_count[vv.x], 1);
            if (p0 < CAP) g_bins[(size_t)vv.x * CAP + p0] = c0;
            int p1 = atomicAdd(&g_count[vv.y], 1);
            if (p1 < CAP) g_bins[(size_t)vv.y * CAP + p1] = c1;
            int p2 = atomicAdd(&g_count[vv.z], 1);
            if (p2 < CAP) g_bins[(size_t)vv.z * CAP + p2] = c2;
            int p3 = atomicAdd(&g_count[vv.w], 1);
            if (p3 < CAP) g_bins[(size_t)vv.w * CAP + p3] = c3;
        }
        // edge tail (n_edges % 4)
        int tail = nquads << 2;
        int k = tail + gtid;
        if (k < n_edges) {
            unsigned c = ((unsigned)widx[k] << SRC_BITS) | (unsigned)u[k];
            int dst = v[k];
            int p = atomicAdd(&g_count[dst], 1);
            if (p < CAP) g_bins[(size_t)dst * CAP + p] = c;
        }
        // target flags
        for (int t = gtid; t < n_targets; t += TOTAL_THREADS)
            g_flag[targets[t]] = 1;
    }

    // ---------------- Grid barrier (sense reversal) ------------------------
    __syncthreads();                    // block's phase-A work complete
    if (threadIdx.x == 0) {
        __threadfence();                // publish bins/counts/flags
        unsigned s = *(volatile unsigned*)&g_sense;   // pre-arrival sense
        unsigned arrived = atomicAdd(&g_bar, 1u) + 1u;
        if (arrived == (unsigned)NBLOCKS) {
            g_bar = 0;
            __threadfence();
            *(volatile unsigned*)&g_sense = s ^ 1u;   // release all waiters
        } else {
            while (*(volatile unsigned*)&g_sense == s)
                __nanosleep(64);
        }
        __threadfence();                // acquire phase-A writes
    }
    __syncthreads();

    // ---------------- Phase B: accumulate (R11 loop, frozen) ---------------
    {
        int warp = gtid >> 5;
        int lane = threadIdx.x & 31;
        int half = lane >> 4;
        int l16  = lane & 15;

        for (int n = warp; n < N_NODES; n += TOTAL_WARPS) {
            const unsigned* __restrict__ bins = g_bins + (size_t)n * CAP;
            const unsigned* __restrict__ hb   = bins + 2 * half;

            int deg  = g_count[n];
            int flag = g_flag[n];
            int2 b0  = *(const int2*)(hb);   // stale entries are valid indices

            if (deg > CAP) deg = CAP;
            float4 acc = make_float4(0.f, 0.f, 0.f, 0.f);

            int i = 0;
            if (deg >= 4) {
                unsigned ca = (unsigned)b0.x;
                unsigned cb = (unsigned)b0.y;
                for (;;) {
                    float4 xa = ld_cg_f4(&x4[(size_t)(ca & SRC_MASK) * D4 + l16]);
                    float4 wa = ld_ca_f4(&w4[(size_t)(ca >> SRC_BITS)  * D4 + l16]);
                    float4 xb = ld_cg_f4(&x4[(size_t)(cb & SRC_MASK) * D4 + l16]);
                    float4 wb = ld_ca_f4(&w4[(size_t)(cb >> SRC_BITS)  * D4 + l16]);
                    acc.x += xa.x * wa.x; acc.y += xa.y * wa.y;
                    acc.z += xa.z * wa.z; acc.w += xa.w * wa.w;
                    acc.x += xb.x * wb.x; acc.y += xb.y * wb.y;
                    acc.z += xb.z * wb.z; acc.w += xb.w * wb.w;
                    i += 4;
                    if (i + 4 > deg) break;
                    int2 b = *(const int2*)(hb + i);
                    ca = (unsigned)b.x;
                    cb = (unsigned)b.y;
                }
            }
            int rem = deg - i;
            if (rem >= 2) {
                unsigned c = bins[i + half];
                float4 xa = ld_cg_f4(&x4[(size_t)(c & SRC_MASK) * D4 + l16]);
                float4 wa = ld_ca_f4(&w4[(size_t)(c >> SRC_BITS)  * D4 + l16]);
                acc.x += xa.x * wa.x; acc.y += xa.y * wa.y;
                acc.z += xa.z * wa.z; acc.w += xa.w * wa.w;
                i += 2;
                rem -= 2;
            }
            if (rem == 1 && half == 0) {
                unsigned c = bins[i];
                float4 xa = ld_cg_f4(&x4[(size_t)(c & SRC_MASK) * D4 + l16]);
                float4 wa = ld_ca_f4(&w4[(size_t)(c >> SRC_BITS)  * D4 + l16]);
                acc.x += xa.x * wa.x; acc.y += xa.y * wa.y;
                acc.z += xa.z * wa.z; acc.w += xa.w * wa.w;
            }

            acc.x += __shfl_xor_sync(0xffffffffu, acc.x, 16);
            acc.y += __shfl_xor_sync(0xffffffffu, acc.y, 16);
            acc.z += __shfl_xor_sync(0xffffffffu, acc.z, 16);
            acc.w += __shfl_xor_sync(0xffffffffu, acc.w, 16);

            if (half == 0) {
                if (!flag) {
                    float4 xn = ld_cg_f4(&x4[(size_t)n * D4 + l16]);
                    acc.x += xn.x; acc.y += xn.y; acc.z += xn.z; acc.w += xn.w;
                }
                out4[(size_t)n * D4 + l16] = acc;
            }

            if (lane == 0) {     // reset scratch for the next replay
                g_count[n] = 0;
                g_flag[n]  = 0;
            }
        }
    }
}

// ---------------------------------------------------------------------------
extern "C" void kernel_launch(void* const* d_in, const int* in_sizes, int n_in,
                              void* d_out, int out_size) {
    const float* x       = (const float*)d_in[0];
    const float* weights = (const float*)d_in[1];
    const int*   u       = (const int*)d_in[2];
    const int*   v       = (const int*)d_in[3];
    const int*   widx    = (const int*)d_in[4];
    const int*   targets = (const int*)d_in[5];
    float* out = (float*)d_out;

    int n_edges   = in_sizes[2];
    int n_targets = in_sizes[5];

    fused_kernel<<<NBLOCKS, NTHREADS>>>((const float4*)x,
                                        (const float4*)weights,
                                        u, v, widx, targets,
                                        (float4*)out,
                                        n_edges, n_targets);
}

// round 13
// speedup vs baseline: 1.1057x; 1.1057x over previous
#include <cuda_runtime.h>
#include <cstdint>

// N=100000 nodes, D=64 feats, E=1250000 edges, W=1024, T=20000 targets.
static constexpr int N_NODES = 100000;
static constexpr int D4 = 16;       // float4 per row (64 floats)
static constexpr int CAP = 64;      // per-node bin capacity (P(deg>=64) ~ 1e-23)

// Persistent accumulate grid: 14 blocks/SM x 148 SMs (36-reg budget via
// __launch_bounds__(128,14) -> 56 warps/SM, single wave, headroom for the
// bins-prefetch registers without spill).
static constexpr int ACC_BLOCKS  = 2072;   // 148 * 14
static constexpr int ACC_THREADS = 128;
static constexpr int ACC_WARPS   = ACC_BLOCKS * (ACC_THREADS / 32);  // 8288

// Packed edge entry: src in bits [0,17), widx in bits [17,27).
static constexpr int SRC_BITS = 17;
static constexpr unsigned SRC_MASK = (1u << SRC_BITS) - 1u;

// Scratch. Zero-initialized at load; accumulate resets count/flag per node.
__device__ int      g_count[N_NODES];
__device__ int      g_flag[N_NODES];
__device__ unsigned g_bins[(size_t)N_NODES * CAP];   // packed (widx<<17)|src

// x gather: bypass L1 (streaming) -> L2 only
__device__ __forceinline__ float4 ld_cg_f4(const float4* p) {
    float4 r;
    asm volatile("ld.global.cg.v4.f32 {%0, %1, %2, %3}, [%4];"
                 : "=f"(r.x), "=f"(r.y), "=f"(r.z), "=f"(r.w) : "l"(p));
    return r;
}
// w gather: cache in L1 (256KB hot working set)
__device__ __forceinline__ float4 ld_ca_f4(const float4* p) {
    float4 r;
    asm volatile("ld.global.ca.v4.f32 {%0, %1, %2, %3}, [%4];"
                 : "=f"(r.x), "=f"(r.y), "=f"(r.z), "=f"(r.w) : "l"(p));
    return r;
}

// ---------------------------------------------------------------------------
// K1: bin edges by destination (4 edges/thread, int4 loads);
// low-index threads also set target flags (4/thread).
// ---------------------------------------------------------------------------
__global__ void scatter_kernel(const int* __restrict__ u,
                               const int* __restrict__ v,
                               const int* __restrict__ widx,
                               const int* __restrict__ targets,
                               int n_edges, int n_targets) {
    int t = blockIdx.x * blockDim.x + threadIdx.x;
    int e = t * 4;
    if (e >= n_edges) return;

    int ti = t * 4;
    if (ti + 3 < n_targets) {
        int4 tg = *(const int4*)(targets + ti);
        g_flag[tg.x] = 1; g_flag[tg.y] = 1;
        g_flag[tg.z] = 1; g_flag[tg.w] = 1;
    } else {
        for (int k = ti; k < n_targets && k < ti + 4; ++k)
            g_flag[targets[k]] = 1;
    }

    if (e + 3 < n_edges) {
        int4 uu = *(const int4*)(u + e);
        int4 vv = *(const int4*)(v + e);
        int4 ww = *(const int4*)(widx + e);
        unsigned c0 = ((unsigned)ww.x << SRC_BITS) | (unsigned)uu.x;
        unsigned c1 = ((unsigned)ww.y << SRC_BITS) | (unsigned)uu.y;
        unsigned c2 = ((unsigned)ww.z << SRC_BITS) | (unsigned)uu.z;
        unsigned c3 = ((unsigned)ww.w << SRC_BITS) | (unsigned)uu.w;
        int p0 = atomicAdd(&g_count[vv.x], 1);
        if (p0 < CAP) g_bins[(size_t)vv.x * CAP + p0] = c0;
        int p1 = atomicAdd(&g_count[vv.y], 1);
        if (p1 < CAP) g_bins[(size_t)vv.y * CAP + p1] = c1;
        int p2 = atomicAdd(&g_count[vv.z], 1);
        if (p2 < CAP) g_bins[(size_t)vv.z * CAP + p2] = c2;
        int p3 = atomicAdd(&g_count[vv.w], 1);
        if (p3 < CAP) g_bins[(size_t)vv.w * CAP + p3] = c3;
    } else {
        for (int k = e; k < n_edges; ++k) {
            unsigned c = ((unsigned)widx[k] << SRC_BITS) | (unsigned)u[k];
            int dst = v[k];
            int p = atomicAdd(&g_count[dst], 1);
            if (p < CAP) g_bins[(size_t)dst * CAP + p] = c;
        }
    }
}

// ---------------------------------------------------------------------------
// K2: persistent grid; one node per warp; float4 lanes with paired-edge
// loads. Software pipeline on bin metadata: the NEXT batch's int2 is loaded
// BEFORE the current batch's gathers, overlapping the bins->gather L2
// latencies of consecutive iterations. shfl_xor(16) combines halves.
// ---------------------------------------------------------------------------
__global__ void __launch_bounds__(ACC_THREADS, 14)
accumulate_kernel(const float4* __restrict__ x4,
                  const float4* __restrict__ w4,
                  float4* __restrict__ out4) {
    int warp = (blockIdx.x * blockDim.x + threadIdx.x) >> 5;
    int lane = threadIdx.x & 31;
    int half = lane >> 4;          // 0 or 1
    int l16  = lane & 15;          // float4 slot within the row

    for (int n = warp; n < N_NODES; n += ACC_WARPS) {
        const unsigned* __restrict__ bins = g_bins + (size_t)n * CAP;
        const unsigned* __restrict__ hb   = bins + 2 * half;  // this half's lane

        // independent prologue loads (latencies overlap)
        int deg  = g_count[n];
        int flag = g_flag[n];
        int2 b0  = *(const int2*)(hb);   // stale entries are valid indices

        if (deg > CAP) deg = CAP;
        float4 acc = make_float4(0.f, 0.f, 0.f, 0.f);

        int i = 0;
        if (deg >= 4) {
            unsigned ca = (unsigned)b0.x;
            unsigned cb = (unsigned)b0.y;
            for (;;) {
                // prefetch NEXT batch's metadata before this batch's gathers
                bool has_next = (i + 8 <= deg);
                int2 nb;
                if (has_next) nb = *(const int2*)(hb + i + 4);

                float4 xa = ld_cg_f4(&x4[(size_t)(ca & SRC_MASK) * D4 + l16]);
                float4 wa = ld_ca_f4(&w4[(size_t)(ca >> SRC_BITS)  * D4 + l16]);
                float4 xb = ld_cg_f4(&x4[(size_t)(cb & SRC_MASK) * D4 + l16]);
                float4 wb = ld_ca_f4(&w4[(size_t)(cb >> SRC_BITS)  * D4 + l16]);
                acc.x += xa.x * wa.x; acc.y += xa.y * wa.y;
                acc.z += xa.z * wa.z; acc.w += xa.w * wa.w;
                acc.x += xb.x * wb.x; acc.y += xb.y * wb.y;
                acc.z += xb.z * wb.z; acc.w += xb.w * wb.w;

                i += 4;
                if (!has_next) break;
                ca = (unsigned)nb.x;
                cb = (unsigned)nb.y;
            }
        }
        // remainder 0-3 edges
        int rem = deg - i;
        if (rem >= 2) {
            unsigned c = bins[i + half];   // one edge per half
            float4 xa = ld_cg_f4(&x4[(size_t)(c & SRC_MASK) * D4 + l16]);
            float4 wa = ld_ca_f4(&w4[(size_t)(c >> SRC_BITS)  * D4 + l16]);
            acc.x += xa.x * wa.x; acc.y += xa.y * wa.y;
            acc.z += xa.z * wa.z; acc.w += xa.w * wa.w;
            i += 2;
            rem -= 2;
        }
        if (rem == 1 && half == 0) {
            unsigned c = bins[i];
            float4 xa = ld_cg_f4(&x4[(size_t)(c & SRC_MASK) * D4 + l16]);
            float4 wa = ld_ca_f4(&w4[(size_t)(c >> SRC_BITS)  * D4 + l16]);
            acc.x += xa.x * wa.x; acc.y += xa.y * wa.y;
            acc.z += xa.z * wa.z; acc.w += xa.w * wa.w;
        }

        // combine halves (all lanes converged)
        acc.x += __shfl_xor_sync(0xffffffffu, acc.x, 16);
        acc.y += __shfl_xor_sync(0xffffffffu, acc.y, 16);
        acc.z += __shfl_xor_sync(0xffffffffu, acc.z, 16);
        acc.w += __shfl_xor_sync(0xffffffffu, acc.w, 16);

        if (half == 0) {
            if (!flag) {
                float4 xn = ld_cg_f4(&x4[(size_t)n * D4 + l16]);
                acc.x += xn.x; acc.y += xn.y; acc.z += xn.z; acc.w += xn.w;
            }
            out4[(size_t)n * D4 + l16] = acc;
        }

        if (lane == 0) {         // reset scratch for the next replay
            g_count[n] = 0;
            g_flag[n]  = 0;
        }
    }
}

// ---------------------------------------------------------------------------
extern "C" void kernel_launch(void* const* d_in, const int* in_sizes, int n_in,
                              void* d_out, int out_size) {
    const float* x       = (const float*)d_in[0];
    const float* weights = (const float*)d_in[1];
    const int*   u       = (const int*)d_in[2];
    const int*   v       = (const int*)d_in[3];
    const int*   widx    = (const int*)d_in[4];
    const int*   targets = (const int*)d_in[5];
    float* out = (float*)d_out;

    int n_edges   = in_sizes[2];
    int n_targets = in_sizes[5];

    {
        int work = (n_edges + 3) / 4;
        int threads = 256;
        int blocks = (work + threads - 1) / threads;
        scatter_kernel<<<blocks, threads>>>(u, v, widx, targets,
                                            n_edges, n_targets);
    }
    accumulate_kernel<<<ACC_BLOCKS, ACC_THREADS>>>((const float4*)x,
                                                   (const float4*)weights,
                                                   (float4*)out);
}

// round 14
// speedup vs baseline: 1.1432x; 1.0339x over previous
#include <cuda_runtime.h>
#include <cstdint>

// N=100000 nodes, D=64 feats, E=1250000 edges, W=1024, T=20000 targets.
static constexpr int N_NODES = 100000;
static constexpr int D4 = 16;       // float4 per row (64 floats)
static constexpr int CAP = 64;      // per-node bin capacity (P(deg>=64) ~ 1e-23)

// Persistent accumulate grid: 16 blocks/SM x 148 SMs. The loop compiles to
// 31 regs, so 64 warps/SM fit (full register file) -> single wave, max occ.
static constexpr int ACC_BLOCKS  = 2368;   // 148 * 16
static constexpr int ACC_THREADS = 128;
static constexpr int ACC_WARPS   = ACC_BLOCKS * (ACC_THREADS / 32);  // 9472

// Packed edge entry: src in bits [0,17), widx in bits [17,27).
static constexpr int SRC_BITS = 17;
static constexpr unsigned SRC_MASK = (1u << SRC_BITS) - 1u;

// Scratch. Zero-initialized at load; accumulate resets count/flag per node.
__device__ int      g_count[N_NODES];
__device__ int      g_flag[N_NODES];
__device__ unsigned g_bins[(size_t)N_NODES * CAP];   // packed (widx<<17)|src

// x gather: bypass L1 (streaming) -> L2 only
__device__ __forceinline__ float4 ld_cg_f4(const float4* p) {
    float4 r;
    asm volatile("ld.global.cg.v4.f32 {%0, %1, %2, %3}, [%4];"
                 : "=f"(r.x), "=f"(r.y), "=f"(r.z), "=f"(r.w) : "l"(p));
    return r;
}
// w gather: cache in L1 (256KB hot working set)
__device__ __forceinline__ float4 ld_ca_f4(const float4* p) {
    float4 r;
    asm volatile("ld.global.ca.v4.f32 {%0, %1, %2, %3}, [%4];"
                 : "=f"(r.x), "=f"(r.y), "=f"(r.z), "=f"(r.w) : "l"(p));
    return r;
}

// ---------------------------------------------------------------------------
// K1: bin edges by destination (4 edges/thread, int4 loads);
// low-index threads also set target flags (4/thread).
// ---------------------------------------------------------------------------
__global__ void scatter_kernel(const int* __restrict__ u,
                               const int* __restrict__ v,
                               const int* __restrict__ widx,
                               const int* __restrict__ targets,
                               int n_edges, int n_targets) {
    int t = blockIdx.x * blockDim.x + threadIdx.x;
    int e = t * 4;
    if (e >= n_edges) return;

    int ti = t * 4;
    if (ti + 3 < n_targets) {
        int4 tg = *(const int4*)(targets + ti);
        g_flag[tg.x] = 1; g_flag[tg.y] = 1;
        g_flag[tg.z] = 1; g_flag[tg.w] = 1;
    } else {
        for (int k = ti; k < n_targets && k < ti + 4; ++k)
            g_flag[targets[k]] = 1;
    }

    if (e + 3 < n_edges) {
        int4 uu = *(const int4*)(u + e);
        int4 vv = *(const int4*)(v + e);
        int4 ww = *(const int4*)(widx + e);
        unsigned c0 = ((unsigned)ww.x << SRC_BITS) | (unsigned)uu.x;
        unsigned c1 = ((unsigned)ww.y << SRC_BITS) | (unsigned)uu.y;
        unsigned c2 = ((unsigned)ww.z << SRC_BITS) | (unsigned)uu.z;
        unsigned c3 = ((unsigned)ww.w << SRC_BITS) | (unsigned)uu.w;
        int p0 = atomicAdd(&g_count[vv.x], 1);
        if (p0 < CAP) g_bins[(size_t)vv.x * CAP + p0] = c0;
        int p1 = atomicAdd(&g_count[vv.y], 1);
        if (p1 < CAP) g_bins[(size_t)vv.y * CAP + p1] = c1;
        int p2 = atomicAdd(&g_count[vv.z], 1);
        if (p2 < CAP) g_bins[(size_t)vv.z * CAP + p2] = c2;
        int p3 = atomicAdd(&g_count[vv.w], 1);
        if (p3 < CAP) g_bins[(size_t)vv.w * CAP + p3] = c3;
    } else {
        for (int k = e; k < n_edges; ++k) {
            unsigned c = ((unsigned)widx[k] << SRC_BITS) | (unsigned)u[k];
            int dst = v[k];
            int p = atomicAdd(&g_count[dst], 1);
            if (p < CAP) g_bins[(size_t)dst * CAP + p] = c;
        }
    }
}

// ---------------------------------------------------------------------------
// K2: persistent grid at FULL occupancy (64 warps/SM, 31 regs); one node per
// warp; float4 lanes with paired-edge loads; next-batch metadata prefetched
// before the current batch's gathers. shfl_xor(16) combines halves.
// ---------------------------------------------------------------------------
__global__ void __launch_bounds__(ACC_THREADS, 16)
accumulate_kernel(const float4* __restrict__ x4,
                  const float4* __restrict__ w4,
                  float4* __restrict__ out4) {
    int warp = (blockIdx.x * blockDim.x + threadIdx.x) >> 5;
    int lane = threadIdx.x & 31;
    int half = lane >> 4;          // 0 or 1
    int l16  = lane & 15;          // float4 slot within the row

    for (int n = warp; n < N_NODES; n += ACC_WARPS) {
        const unsigned* __restrict__ bins = g_bins + (size_t)n * CAP;
        const unsigned* __restrict__ hb   = bins + 2 * half;  // this half's lane

        // independent prologue loads (latencies overlap)
        int deg  = g_count[n];
        int flag = g_flag[n];
        int2 b0  = *(const int2*)(hb);   // stale entries are valid indices

        if (deg > CAP) deg = CAP;
        float4 acc = make_float4(0.f, 0.f, 0.f, 0.f);

        int i = 0;
        if (deg >= 4) {
            unsigned ca = (unsigned)b0.x;
            unsigned cb = (unsigned)b0.y;
            for (;;) {
                // prefetch NEXT batch's metadata before this batch's gathers
                bool has_next = (i + 8 <= deg);
                int2 nb;
                if (has_next) nb = *(const int2*)(hb + i + 4);

                float4 xa = ld_cg_f4(&x4[(size_t)(ca & SRC_MASK) * D4 + l16]);
                float4 wa = ld_ca_f4(&w4[(size_t)(ca >> SRC_BITS)  * D4 + l16]);
                float4 xb = ld_cg_f4(&x4[(size_t)(cb & SRC_MASK) * D4 + l16]);
                float4 wb = ld_ca_f4(&w4[(size_t)(cb >> SRC_BITS)  * D4 + l16]);
                acc.x += xa.x * wa.x; acc.y += xa.y * wa.y;
                acc.z += xa.z * wa.z; acc.w += xa.w * wa.w;
                acc.x += xb.x * wb.x; acc.y += xb.y * wb.y;
                acc.z += xb.z * wb.z; acc.w += xb.w * wb.w;

                i += 4;
                if (!has_next) break;
                ca = (unsigned)nb.x;
                cb = (unsigned)nb.y;
            }
        }
        // remainder 0-3 edges
        int rem = deg - i;
        if (rem >= 2) {
            unsigned c = bins[i + half];   // one edge per half
            float4 xa = ld_cg_f4(&x4[(size_t)(c & SRC_MASK) * D4 + l16]);
            float4 wa = ld_ca_f4(&w4[(size_t)(c >> SRC_BITS)  * D4 + l16]);
            acc.x += xa.x * wa.x; acc.y += xa.y * wa.y;
            acc.z += xa.z * wa.z; acc.w += xa.w * wa.w;
            i += 2;
            rem -= 2;
        }
        if (rem == 1 && half == 0) {
            unsigned c = bins[i];
            float4 xa = ld_cg_f4(&x4[(size_t)(c & SRC_MASK) * D4 + l16]);
            float4 wa = ld_ca_f4(&w4[(size_t)(c >> SRC_BITS)  * D4 + l16]);
            acc.x += xa.x * wa.x; acc.y += xa.y * wa.y;
            acc.z += xa.z * wa.z; acc.w += xa.w * wa.w;
        }

        // combine halves (all lanes converged)
        acc.x += __shfl_xor_sync(0xffffffffu, acc.x, 16);
        acc.y += __shfl_xor_sync(0xffffffffu, acc.y, 16);
        acc.z += __shfl_xor_sync(0xffffffffu, acc.z, 16);
        acc.w += __shfl_xor_sync(0xffffffffu, acc.w, 16);

        if (half == 0) {
            if (!flag) {
                float4 xn = ld_cg_f4(&x4[(size_t)n * D4 + l16]);
                acc.x += xn.x; acc.y += xn.y; acc.z += xn.z; acc.w += xn.w;
            }
            out4[(size_t)n * D4 + l16] = acc;
        }

        if (lane == 0) {         // reset scratch for the next replay
            g_count[n] = 0;
            g_flag[n]  = 0;
        }
    }
}

// ---------------------------------------------------------------------------
extern "C" void kernel_launch(void* const* d_in, const int* in_sizes, int n_in,
                              void* d_out, int out_size) {
    const float* x       = (const float*)d_in[0];
    const float* weights = (const float*)d_in[1];
    const int*   u       = (const int*)d_in[2];
    const int*   v       = (const int*)d_in[3];
    const int*   widx    = (const int*)d_in[4];
    const int*   targets = (const int*)d_in[5];
    float* out = (float*)d_out;

    int n_edges   = in_sizes[2];
    int n_targets = in_sizes[5];

    {
        int work = (n_edges + 3) / 4;
        int threads = 256;
        int blocks = (work + threads - 1) / threads;
        scatter_kernel<<<blocks, threads>>>(u, v, widx, targets,
                                            n_edges, n_targets);
    }
    accumulate_kernel<<<ACC_BLOCKS, ACC_THREADS>>>((const float4*)x,
                                                   (const float4*)weights,
                                                   (float4*)out);
}